// round 1
// baseline (speedup 1.0000x reference)
#include <cuda_runtime.h>
#include <cuda_bf16.h>
#include <math_constants.h>

// Problem constants
// x: [16,5,4,45,45,45] -> fold to N=80 samples
// stage0: conv 4->32 k5 pad1 (43^3) + prelu + pool2 -> [80,32,21,21,21]
// stage1: conv 32->32 k5 pad1 (19^3) + prelu + pool2 -> [80,32,9,9,9]
// stage2: conv 32->64 k4 pad1 (8^3)  + prelu + pool2 -> [80,64,4,4,4]
// stage3: conv 64->64 k3 pad0 (2^3)  + prelu -> feat [80,512]
// fc1: cat(feat, mean_agents) 1024 -> 256 (+prelu)
// fc2: 512 -> 128 (+prelu)
// fc3: 256 -> 6  -> out [16,5,6]

#define NTOT 80

__device__ float g_h0[80 * 32 * 21 * 21 * 21];   // 94.8 MB
__device__ float g_h1[80 * 32 * 9 * 9 * 9];
__device__ float g_h2[80 * 64 * 64];
__device__ float g_feat[80 * 512];
__device__ float g_f1[80 * 256];
__device__ float g_f2[80 * 128];

// ---------------------------------------------------------------------------
// Stage 0: conv(4->32,k5,p1) + prelu + maxpool2, fused.
// grid (pz=21, ocpair=16, n=80), block 448 (441 active: 21x21 pooled y,x)
// dynamic smem: input tile 6 z-planes of 46x48 + 1000 weights
// ---------------------------------------------------------------------------
__global__ __launch_bounds__(448) void conv0_kernel(
    const float* __restrict__ x, const float* __restrict__ w,
    const float* __restrict__ bias, const float* __restrict__ alpha)
{
    extern __shared__ float smem0[];
    float* s_in = smem0;              // 6*46*48 = 13248
    float* s_w  = smem0 + 13248;      // 2*4*125 = 1000

    const int pz = blockIdx.x;
    const int op = blockIdx.y;
    const int n  = blockIdx.z;
    const int tid = threadIdx.x;

    for (int t = tid; t < 1000; t += 448) {
        int o = t / 500, r = t % 500;
        s_w[t] = w[(op * 2 + o) * 500 + r];
    }

    float acc[16];
#pragma unroll
    for (int i = 0; i < 16; i++) acc[i] = 0.f;

    const int py = tid / 21, px = tid % 21;
    const bool active = tid < 441;

    for (int ic = 0; ic < 4; ic++) {
        __syncthreads();
        const float* xin = x + (n * 4 + ic) * 91125;
        for (int t = tid; t < 6 * 46 * 48; t += 448) {
            int zz = t / (46 * 48);
            int r  = t % (46 * 48);
            int yy = r / 48, xx = r % 48;
            int iz = 2 * pz - 1 + zz, iy = yy - 1, ix = xx - 1;
            float v = 0.f;
            if (xx < 46 && (unsigned)iz < 45u && (unsigned)iy < 45u && (unsigned)ix < 45u)
                v = xin[iz * 2025 + iy * 45 + ix] * (1.0f / 255.0f);
            s_in[t] = v;
        }
        __syncthreads();
        if (!active) continue;

        const float* wb0 = s_w + ic * 125;
        const float* wb1 = s_w + 500 + ic * 125;
#pragma unroll 1
        for (int kz = 0; kz < 5; kz++) {
#pragma unroll
            for (int ky = 0; ky < 5; ky++) {
                float wa[5], wbq[5];
#pragma unroll
                for (int kx = 0; kx < 5; kx++) {
                    wa[kx]  = wb0[(kz * 5 + ky) * 5 + kx];
                    wbq[kx] = wb1[(kz * 5 + ky) * 5 + kx];
                }
#pragma unroll
                for (int dz = 0; dz < 2; dz++) {
#pragma unroll
                    for (int dy = 0; dy < 2; dy++) {
                        const float* row = s_in + (kz + dz) * (46 * 48)
                                         + (2 * py + dy + ky) * 48 + 2 * px;
                        float v[6];
#pragma unroll
                        for (int j = 0; j < 6; j++) v[j] = row[j];
                        const int ai = dz * 4 + dy * 2;
#pragma unroll
                        for (int kx = 0; kx < 5; kx++) {
                            acc[ai + 0]     += wa[kx]  * v[kx];
                            acc[ai + 1]     += wa[kx]  * v[kx + 1];
                            acc[8 + ai + 0] += wbq[kx] * v[kx];
                            acc[8 + ai + 1] += wbq[kx] * v[kx + 1];
                        }
                    }
                }
            }
        }
    }

    if (active) {
        const float a = alpha[0];
#pragma unroll
        for (int o = 0; o < 2; o++) {
            float bs = bias[op * 2 + o];
            float m = -CUDART_INF_F;
#pragma unroll
            for (int j = 0; j < 8; j++) {
                float t = acc[o * 8 + j] + bs;
                t = t >= 0.f ? t : a * t;
                m = fmaxf(m, t);
            }
            g_h0[((n * 32 + op * 2 + o) * 21 + pz) * 441 + py * 21 + px] = m;
        }
    }
}

// ---------------------------------------------------------------------------
// Stage 1: conv(32->32,k5,p1) + prelu + maxpool2, fused.
// grid (ocpair=16, n=80), block 256 (243 active). Each thread: 3 pooled z.
// smem: padded input channel 22x24x22 + 250 weights (static, 47.4 KB)
// ---------------------------------------------------------------------------
__global__ __launch_bounds__(256) void conv1_kernel(
    const float* __restrict__ w, const float* __restrict__ bias,
    const float* __restrict__ alpha)
{
    __shared__ float s_in[22 * 24 * 22];  // 11616
    __shared__ float s_w[250];

    const int op = blockIdx.x;
    const int n  = blockIdx.y;
    const int tid = threadIdx.x;

    float acc[48];
#pragma unroll
    for (int i = 0; i < 48; i++) acc[i] = 0.f;

    const int q = tid / 81;
    const int rr = tid % 81;
    const int py = rr / 9, px = rr % 9;
    const bool active = tid < 243;

    for (int ic = 0; ic < 32; ic++) {
        __syncthreads();
        for (int t = tid; t < 250; t += 256) {
            int o = t / 125, r = t % 125;
            s_w[t] = w[((op * 2 + o) * 32 + ic) * 125 + r];
        }
        const float* hin = g_h0 + (n * 32 + ic) * 9261;
        for (int t = tid; t < 11616; t += 256) {
            int zz = t / 528;
            int r  = t % 528;
            int yy = r / 24, xx = r % 24;
            int iz = zz - 1, iy = yy - 1, ix = xx - 1;
            float v = 0.f;
            if (xx < 22 && (unsigned)iz < 21u && (unsigned)iy < 21u && (unsigned)ix < 21u)
                v = hin[iz * 441 + iy * 21 + ix];
            s_in[t] = v;
        }
        __syncthreads();
        if (!active) continue;

#pragma unroll 1
        for (int kz = 0; kz < 5; kz++) {
#pragma unroll
            for (int ky = 0; ky < 5; ky++) {
                float wa[5], wbq[5];
#pragma unroll
                for (int kx = 0; kx < 5; kx++) {
                    wa[kx]  = s_w[(kz * 5 + ky) * 5 + kx];
                    wbq[kx] = s_w[125 + (kz * 5 + ky) * 5 + kx];
                }
#pragma unroll
                for (int j = 0; j < 3; j++) {
                    const int pz = q * 3 + j;
#pragma unroll
                    for (int dz = 0; dz < 2; dz++) {
#pragma unroll
                        for (int dy = 0; dy < 2; dy++) {
                            const float* row = s_in + (2 * pz + dz + kz) * 528
                                             + (2 * py + dy + ky) * 24 + 2 * px;
                            float v[6];
#pragma unroll
                            for (int jj = 0; jj < 6; jj++) v[jj] = row[jj];
                            const int ai = j * 8 + dz * 4 + dy * 2;
#pragma unroll
                            for (int kx = 0; kx < 5; kx++) {
                                acc[ai + 0]      += wa[kx]  * v[kx];
                                acc[ai + 1]      += wa[kx]  * v[kx + 1];
                                acc[24 + ai + 0] += wbq[kx] * v[kx];
                                acc[24 + ai + 1] += wbq[kx] * v[kx + 1];
                            }
                        }
                    }
                }
            }
        }
    }

    if (active) {
        const float a = alpha[0];
#pragma unroll
        for (int o = 0; o < 2; o++) {
            float bs = bias[op * 2 + o];
#pragma unroll
            for (int j = 0; j < 3; j++) {
                const int pz = q * 3 + j;
                float m = -CUDART_INF_F;
#pragma unroll
                for (int t = 0; t < 8; t++) {
                    float v = acc[o * 24 + j * 8 + t] + bs;
                    v = v >= 0.f ? v : a * v;
                    m = fmaxf(m, v);
                }
                g_h1[(n * 32 + op * 2 + o) * 729 + pz * 81 + py * 9 + px] = m;
            }
        }
    }
}

// ---------------------------------------------------------------------------
// Stage 2: conv(32->64,k4,p1) + prelu + maxpool2, fused.
// grid (oc=64, n=80), block 64 (one thread per pooled output)
// ---------------------------------------------------------------------------
__global__ __launch_bounds__(64) void conv2_kernel(
    const float* __restrict__ w, const float* __restrict__ bias,
    const float* __restrict__ alpha)
{
    __shared__ float s_in[11 * 12 * 11];  // 1452
    __shared__ float s_w2[64];

    const int oc = blockIdx.x;
    const int n  = blockIdx.y;
    const int tid = threadIdx.x;
    const int pz = tid >> 4, py = (tid >> 2) & 3, px = tid & 3;

    float acc[8];
#pragma unroll
    for (int i = 0; i < 8; i++) acc[i] = 0.f;

    for (int ic = 0; ic < 32; ic++) {
        __syncthreads();
        s_w2[tid] = w[(oc * 32 + ic) * 64 + tid];
        const float* hin = g_h1 + (n * 32 + ic) * 729;
        for (int t = tid; t < 1452; t += 64) {
            int zz = t / 132;
            int r  = t % 132;
            int yy = r / 12, xx = r % 12;
            int iz = zz - 1, iy = yy - 1, ix = xx - 1;
            float v = 0.f;
            if (xx < 11 && (unsigned)iz < 9u && (unsigned)iy < 9u && (unsigned)ix < 9u)
                v = hin[iz * 81 + iy * 9 + ix];
            s_in[t] = v;
        }
        __syncthreads();

#pragma unroll
        for (int kz = 0; kz < 4; kz++) {
#pragma unroll
            for (int ky = 0; ky < 4; ky++) {
                float wv[4];
#pragma unroll
                for (int kx = 0; kx < 4; kx++) wv[kx] = s_w2[(kz * 4 + ky) * 4 + kx];
#pragma unroll
                for (int dz = 0; dz < 2; dz++) {
#pragma unroll
                    for (int dy = 0; dy < 2; dy++) {
                        const float* row = s_in + (2 * pz + dz + kz) * 132
                                         + (2 * py + dy + ky) * 12 + 2 * px;
                        float v[5];
#pragma unroll
                        for (int j = 0; j < 5; j++) v[j] = row[j];
                        const int ai = dz * 4 + dy * 2;
#pragma unroll
                        for (int kx = 0; kx < 4; kx++) {
                            acc[ai + 0] += wv[kx] * v[kx];
                            acc[ai + 1] += wv[kx] * v[kx + 1];
                        }
                    }
                }
            }
        }
    }

    const float a = alpha[0];
    float bs = bias[oc];
    float m = -CUDART_INF_F;
#pragma unroll
    for (int j = 0; j < 8; j++) {
        float t = acc[j] + bs;
        t = t >= 0.f ? t : a * t;
        m = fmaxf(m, t);
    }
    g_h2[(n * 64 + oc) * 64 + tid] = m;
}

// ---------------------------------------------------------------------------
// Stage 3: conv(64->64,k3,p0) + prelu -> feat [80,512]
// grid (n=80), block 512 = 64 oc x 8 positions
// ---------------------------------------------------------------------------
__global__ __launch_bounds__(512) void conv3_kernel(
    const float* __restrict__ w, const float* __restrict__ bias,
    const float* __restrict__ alpha)
{
    __shared__ float s_in[4096];
    const int n = blockIdx.x;
    const int tid = threadIdx.x;

    for (int t = tid; t < 4096; t += 512) s_in[t] = g_h2[n * 4096 + t];
    __syncthreads();

    const int oc = tid >> 3, pos = tid & 7;
    const int z = pos >> 2, y = (pos >> 1) & 1, x0 = pos & 1;

    float acc = bias[oc];
    const float* wr = w + oc * (64 * 27);
    for (int ic = 0; ic < 64; ic++) {
        const float* si = s_in + ic * 64;
        const float* wi = wr + ic * 27;
#pragma unroll
        for (int kz = 0; kz < 3; kz++)
#pragma unroll
            for (int ky = 0; ky < 3; ky++)
#pragma unroll
                for (int kx = 0; kx < 3; kx++)
                    acc += wi[(kz * 3 + ky) * 3 + kx]
                         * si[(z + kz) * 16 + (y + ky) * 4 + (x0 + kx)];
    }
    const float a = alpha[0];
    acc = acc >= 0.f ? acc : a * acc;
    g_feat[n * 512 + tid] = acc;
}

// ---------------------------------------------------------------------------
// Comm-FC: out[b,a,o] = sum_i cat(feat[b,a,:], mean_a feat[b,:,:])[i] * w[a,o,i] + b[a,o]
// ---------------------------------------------------------------------------
__device__ __forceinline__ void fc_body(
    const float* __restrict__ fin, const float* __restrict__ w,
    const float* __restrict__ bias, const float* __restrict__ alpha,
    float* __restrict__ fout, int D, int O)
{
    __shared__ float cat[1024];
    const int n = blockIdx.x;
    const int b = n / 5, a = n % 5;
    const int tid = threadIdx.x;

    for (int i = tid; i < D; i += 256) {
        cat[i] = fin[n * D + i];
        float s = 0.f;
#pragma unroll
        for (int a2 = 0; a2 < 5; a2++) s += fin[(b * 5 + a2) * D + i];
        cat[D + i] = s * 0.2f;
    }
    __syncthreads();

    if (tid < O) {
        float accv = bias[a * O + tid];
        const float4* w4 = (const float4*)(w + (size_t)(a * O + tid) * (2 * D));
        const float4* c4 = (const float4*)cat;
        float4 s4 = make_float4(0.f, 0.f, 0.f, 0.f);
        const int n4 = (2 * D) / 4;
        for (int i = 0; i < n4; i++) {
            float4 wv = w4[i];
            float4 cv = c4[i];
            s4.x += wv.x * cv.x; s4.y += wv.y * cv.y;
            s4.z += wv.z * cv.z; s4.w += wv.w * cv.w;
        }
        accv += (s4.x + s4.y) + (s4.z + s4.w);
        if (alpha) {
            float al = alpha[0];
            accv = accv >= 0.f ? accv : al * accv;
        }
        fout[n * O + tid] = accv;
    }
}

__global__ __launch_bounds__(256) void fc1_kernel(const float* __restrict__ w,
                                                  const float* __restrict__ b,
                                                  const float* __restrict__ al)
{ fc_body(g_feat, w, b, al, g_f1, 512, 256); }

__global__ __launch_bounds__(256) void fc2_kernel(const float* __restrict__ w,
                                                  const float* __restrict__ b,
                                                  const float* __restrict__ al)
{ fc_body(g_f1, w, b, al, g_f2, 256, 128); }

__global__ __launch_bounds__(256) void fc3_kernel(const float* __restrict__ w,
                                                  const float* __restrict__ b,
                                                  float* __restrict__ out)
{ fc_body(g_f2, w, b, nullptr, out, 128, 6); }

// ---------------------------------------------------------------------------
extern "C" void kernel_launch(void* const* d_in, const int* in_sizes, int n_in,
                              void* d_out, int out_size)
{
    const float* x   = (const float*)d_in[0];
    const float* w0  = (const float*)d_in[1];
    const float* b0  = (const float*)d_in[2];
    const float* a0  = (const float*)d_in[3];
    const float* w1  = (const float*)d_in[4];
    const float* b1  = (const float*)d_in[5];
    const float* a1  = (const float*)d_in[6];
    const float* w2  = (const float*)d_in[7];
    const float* b2  = (const float*)d_in[8];
    const float* a2  = (const float*)d_in[9];
    const float* w3  = (const float*)d_in[10];
    const float* b3  = (const float*)d_in[11];
    const float* a3  = (const float*)d_in[12];
    const float* fw1 = (const float*)d_in[13];
    const float* fb1 = (const float*)d_in[14];
    const float* a4  = (const float*)d_in[15];
    const float* fw2 = (const float*)d_in[16];
    const float* fb2 = (const float*)d_in[17];
    const float* a5  = (const float*)d_in[18];
    const float* fw3 = (const float*)d_in[19];
    const float* fb3 = (const float*)d_in[20];

    const int smem0 = (13248 + 1000) * sizeof(float);
    cudaFuncSetAttribute(conv0_kernel, cudaFuncAttributeMaxDynamicSharedMemorySize, smem0);

    conv0_kernel<<<dim3(21, 16, 80), 448, smem0>>>(x, w0, b0, a0);
    conv1_kernel<<<dim3(16, 80), 256>>>(w1, b1, a1);
    conv2_kernel<<<dim3(64, 80), 64>>>(w2, b2, a2);
    conv3_kernel<<<80, 512>>>(w3, b3, a3);
    fc1_kernel<<<80, 256>>>(fw1, fb1, a4);
    fc2_kernel<<<80, 256>>>(fw2, fb2, a5);
    fc3_kernel<<<80, 256>>>(fw3, fb3, (float*)d_out);
}

// round 6
// speedup vs baseline: 1.0059x; 1.0059x over previous
#include <cuda_runtime.h>
#include <cuda_bf16.h>
#include <math_constants.h>

// CommNet forward, fp32, f32x2-packed conv stack.
// x: [16,5,4,45,45,45] -> N=80 samples
// stage0: conv 4->32 k5 p1 + prelu + pool2 -> [80,32,21,21,21]
// stage1: conv 32->32 k5 p1 + prelu + pool2 -> [80,32,9,9,9]
// stage2: conv 32->64 k4 p1 + prelu + pool2 -> [80,64,4,4,4]
// stage3: conv 64->64 k3 p0 + prelu -> feat [80,512]
// fc1/fc2/fc3 comm layers -> out [16,5,6]

typedef unsigned long long ull;

__device__ __forceinline__ ull pack2(float lo, float hi) {
    ull d; asm("mov.b64 %0, {%1, %2};" : "=l"(d) : "f"(lo), "f"(hi)); return d;
}
__device__ __forceinline__ void unpack2(ull v, float& lo, float& hi) {
    asm("mov.b64 {%0, %1}, %2;" : "=f"(lo), "=f"(hi) : "l"(v));
}
__device__ __forceinline__ void fma2(ull& d, ull a, ull b) {
    asm("fma.rn.f32x2 %0, %1, %2, %0;" : "+l"(d) : "l"(a), "l"(b));
}

__device__ float g_h0[80 * 32 * 21 * 21 * 21];   // 94.8 MB
__device__ float g_h1[80 * 32 * 9 * 9 * 9];
__device__ float g_h2[80 * 64 * 64];
__device__ float g_feat[80 * 512];
__device__ float g_f1[80 * 256];
__device__ float g_f2[80 * 128];

// ---------------------------------------------------------------------------
// Stage 0: conv(4->32,k5,p1) + prelu + maxpool2, fused, f32x2.
// grid (pz=21, ocpair=16, n=80), block 256.
// Active threads: 231 = 21(py) x 11(pxq); each computes 2 pooled x.
// smem: 6 z-planes of 46x48 input + 1000 weights (dynamic, 57KB)
// ---------------------------------------------------------------------------
#define C0_PLANE 2208   // 46*48

__global__ __launch_bounds__(256) void conv0_kernel(
    const float* __restrict__ x, const float* __restrict__ w,
    const float* __restrict__ bias, const float* __restrict__ alpha)
{
    extern __shared__ float sm[];
    float* s_in = sm;                 // 6*2208 = 13248
    float* s_w  = sm + 13248;         // 1000

    const int pz = blockIdx.x;
    const int op = blockIdx.y;
    const int n  = blockIdx.z;
    const int tid = threadIdx.x;

    for (int t = tid; t < 1000; t += 256) {
        int o = t / 500, r = t % 500;
        s_w[t] = w[(op * 2 + o) * 500 + r];
    }

    // loader precompute (div/mod once)
    int goff[9];
#pragma unroll
    for (int j = 0; j < 9; j++) {
        int idx = tid + j * 256;
        int yy = idx / 48, xx = idx % 48;
        bool v = (idx < 2208) && (xx >= 1 && xx <= 45) && (yy >= 1 && yy <= 45);
        goff[j] = v ? ((yy - 1) * 45 + (xx - 1)) : -1;
    }

    const int py = tid / 11, pxq = tid % 11;
    const bool active = tid < 231;

    ull A[2][2][4];
#pragma unroll
    for (int o = 0; o < 2; o++)
#pragma unroll
        for (int X = 0; X < 2; X++)
#pragma unroll
            for (int d = 0; d < 4; d++) A[o][X][d] = 0ull;

    for (int ic = 0; ic < 4; ic++) {
        __syncthreads();
        const float* xin = x + (n * 4 + ic) * 91125;
#pragma unroll
        for (int zz = 0; zz < 6; zz++) {
            int iz = 2 * pz - 1 + zz;
            bool izok = (unsigned)iz < 45u;
            const float* src = xin + iz * 2025;
#pragma unroll
            for (int j = 0; j < 8; j++) {
                float v = (izok && goff[j] >= 0) ? src[goff[j]] * (1.0f / 255.0f) : 0.f;
                s_in[zz * C0_PLANE + tid + j * 256] = v;
            }
            if (tid < 160) {
                float v = (izok && goff[8] >= 0) ? src[goff[8]] * (1.0f / 255.0f) : 0.f;
                s_in[zz * C0_PLANE + tid + 2048] = v;
            }
        }
        __syncthreads();
        if (!active) continue;

        const float* wb0 = s_w + ic * 125;
        const float* wb1 = s_w + 500 + ic * 125;
#pragma unroll 1
        for (int kz = 0; kz < 5; kz++) {
#pragma unroll 1
            for (int ky = 0; ky < 5; ky++) {
                ull wp0[5], wp1[5];
#pragma unroll
                for (int kx = 0; kx < 5; kx++) {
                    float a0 = wb0[(kz * 5 + ky) * 5 + kx];
                    float b0 = wb1[(kz * 5 + ky) * 5 + kx];
                    wp0[kx] = pack2(a0, a0);
                    wp1[kx] = pack2(b0, b0);
                }
#pragma unroll
                for (int dz = 0; dz < 2; dz++) {
#pragma unroll
                    for (int dy = 0; dy < 2; dy++) {
                        const float* row = s_in + (kz + dz) * C0_PLANE
                                         + (2 * py + dy + ky) * 48 + 4 * pxq;
                        const ull* r2 = (const ull*)row;
                        ull e0 = r2[0], e1 = r2[1], e2 = r2[2], e3 = r2[3];
                        float v0, v1, v2, v3, v4, v5, v6, v7;
                        unpack2(e0, v0, v1); unpack2(e1, v2, v3);
                        unpack2(e2, v4, v5); unpack2(e3, v6, v7);
                        ull P[7];
                        P[0] = e0; P[2] = e1; P[4] = e2; P[6] = e3;
                        P[1] = pack2(v1, v2); P[3] = pack2(v3, v4); P[5] = pack2(v5, v6);
                        const int dd = dz * 2 + dy;
#pragma unroll
                        for (int kx = 0; kx < 5; kx++) {
                            fma2(A[0][0][dd], P[kx],     wp0[kx]);
                            fma2(A[1][0][dd], P[kx],     wp1[kx]);
                            fma2(A[0][1][dd], P[kx + 2], wp0[kx]);
                            fma2(A[1][1][dd], P[kx + 2], wp1[kx]);
                        }
                    }
                }
            }
        }
    }

    if (active) {
        const float a = alpha[0];
#pragma unroll
        for (int o = 0; o < 2; o++) {
            float bs = bias[op * 2 + o];
#pragma unroll
            for (int X = 0; X < 2; X++) {
                int pxx = 2 * pxq + X;
                if (pxx < 21) {
                    float m = -CUDART_INF_F;
#pragma unroll
                    for (int dd = 0; dd < 4; dd++) {
                        float lo, hi;
                        unpack2(A[o][X][dd], lo, hi);
                        lo += bs; lo = lo >= 0.f ? lo : a * lo;
                        hi += bs; hi = hi >= 0.f ? hi : a * hi;
                        m = fmaxf(m, fmaxf(lo, hi));
                    }
                    g_h0[((n * 32 + op * 2 + o) * 21 + pz) * 441 + py * 21 + pxx] = m;
                }
            }
        }
    }
}

// ---------------------------------------------------------------------------
// Stage 1: conv(32->32,k5,p1) + prelu + maxpool2, fused, f32x2.
// grid (ocpair=16, n=80), block 256 (243 active, 3 pooled z each).
// smem: padded input channel 22x24x22 + 250 weights (static, 47.4 KB)
// ---------------------------------------------------------------------------
__global__ __launch_bounds__(256) void conv1_kernel(
    const float* __restrict__ w, const float* __restrict__ bias,
    const float* __restrict__ alpha)
{
    __shared__ float s_in[22 * 24 * 22];  // 11616
    __shared__ float s_w[250];

    const int op = blockIdx.x;
    const int n  = blockIdx.y;
    const int tid = threadIdx.x;

    const int q = tid / 81;
    const int rr = tid % 81;
    const int py = rr / 9, px = rr % 9;
    const bool active = tid < 243;

    // weight-loader precompute (div/mod hoisted out of ic loop)
    const bool wload = tid < 250;
    const int w_o = tid / 125, w_r = tid % 125;

    // loader precompute: plane = 528 = 22 rows x 24 cols
    int goff[3];
#pragma unroll
    for (int j = 0; j < 3; j++) {
        int idx = tid + j * 256;
        int yy = idx / 24, xx = idx % 24;
        bool v = (idx < 528) && (xx >= 1 && xx <= 21) && (yy >= 1 && yy <= 21);
        goff[j] = v ? ((yy - 1) * 21 + (xx - 1)) : -1;
    }

    ull A[2][3][4];
#pragma unroll
    for (int o = 0; o < 2; o++)
#pragma unroll
        for (int j = 0; j < 3; j++)
#pragma unroll
            for (int d = 0; d < 4; d++) A[o][j][d] = 0ull;

    for (int ic = 0; ic < 32; ic++) {
        __syncthreads();
        if (wload)
            s_w[tid] = w[((op * 2 + w_o) * 32 + ic) * 125 + w_r];
        const float* hin = g_h0 + (n * 32 + ic) * 9261;
#pragma unroll 1
        for (int zz = 0; zz < 22; zz++) {
            int iz = zz - 1;
            bool ok = (unsigned)iz < 21u;
            const float* src = hin + iz * 441;
            s_in[zz * 528 + tid]       = (ok && goff[0] >= 0) ? src[goff[0]] : 0.f;
            s_in[zz * 528 + 256 + tid] = (ok && goff[1] >= 0) ? src[goff[1]] : 0.f;
            if (tid < 16)
                s_in[zz * 528 + 512 + tid] = (ok && goff[2] >= 0) ? src[goff[2]] : 0.f;
        }
        __syncthreads();
        if (!active) continue;

#pragma unroll 1
        for (int kz = 0; kz < 5; kz++) {
#pragma unroll 1
            for (int ky = 0; ky < 5; ky++) {
                ull wp0[5], wp1[5];
#pragma unroll
                for (int kx = 0; kx < 5; kx++) {
                    float a0 = s_w[(kz * 5 + ky) * 5 + kx];
                    float b0 = s_w[125 + (kz * 5 + ky) * 5 + kx];
                    wp0[kx] = pack2(a0, a0);
                    wp1[kx] = pack2(b0, b0);
                }
#pragma unroll
                for (int j = 0; j < 3; j++) {
                    const int pzz = q * 3 + j;
#pragma unroll
                    for (int dz = 0; dz < 2; dz++) {
#pragma unroll
                        for (int dy = 0; dy < 2; dy++) {
                            const float* row = s_in + (2 * pzz + dz + kz) * 528
                                             + (2 * py + dy + ky) * 24 + 2 * px;
                            const ull* r2 = (const ull*)row;
                            ull e0 = r2[0], e1 = r2[1], e2 = r2[2];
                            float v0, v1, v2, v3, v4, v5;
                            unpack2(e0, v0, v1); unpack2(e1, v2, v3); unpack2(e2, v4, v5);
                            ull P[5];
                            P[0] = e0; P[2] = e1; P[4] = e2;
                            P[1] = pack2(v1, v2); P[3] = pack2(v3, v4);
                            const int dd = dz * 2 + dy;
#pragma unroll
                            for (int kx = 0; kx < 5; kx++) {
                                fma2(A[0][j][dd], P[kx], wp0[kx]);
                                fma2(A[1][j][dd], P[kx], wp1[kx]);
                            }
                        }
                    }
                }
            }
        }
    }

    if (active) {
        const float a = alpha[0];
#pragma unroll
        for (int o = 0; o < 2; o++) {
            float bs = bias[op * 2 + o];
#pragma unroll
            for (int j = 0; j < 3; j++) {
                const int pzz = q * 3 + j;
                float m = -CUDART_INF_F;
#pragma unroll
                for (int dd = 0; dd < 4; dd++) {
                    float lo, hi;
                    unpack2(A[o][j][dd], lo, hi);
                    lo += bs; lo = lo >= 0.f ? lo : a * lo;
                    hi += bs; hi = hi >= 0.f ? hi : a * hi;
                    m = fmaxf(m, fmaxf(lo, hi));
                }
                g_h1[(n * 32 + op * 2 + o) * 729 + pzz * 81 + py * 9 + px] = m;
            }
        }
    }
}

// ---------------------------------------------------------------------------
// Stage 2: conv(32->64,k4,p1) + prelu + maxpool2, fused, f32x2.
// grid (ocpair=32, n=80), block 64 (one thread per pooled output, 2 oc each)
// ---------------------------------------------------------------------------
__global__ __launch_bounds__(64) void conv2_kernel(
    const float* __restrict__ w, const float* __restrict__ bias,
    const float* __restrict__ alpha)
{
    __shared__ float s_in[11 * 132];   // 1452 = 11 z x (11 y x 12 x)
    __shared__ float s_w2[128];

    const int op = blockIdx.x;         // pair of output channels
    const int n  = blockIdx.y;
    const int tid = threadIdx.x;
    const int pz = tid >> 4, py = (tid >> 2) & 3, px = tid & 3;

    // loader precompute: plane 132 = 11 rows x 12 cols
    int goff[3];
#pragma unroll
    for (int j = 0; j < 3; j++) {
        int idx = tid + j * 64;
        int yy = idx / 12, xx = idx % 12;
        bool v = (idx < 132) && (xx >= 1 && xx <= 9) && (yy >= 1 && yy <= 9);
        goff[j] = v ? ((yy - 1) * 9 + (xx - 1)) : -1;
    }

    ull A[2][4];
#pragma unroll
    for (int o = 0; o < 2; o++)
#pragma unroll
        for (int d = 0; d < 4; d++) A[o][d] = 0ull;

    for (int ic = 0; ic < 32; ic++) {
        __syncthreads();
        s_w2[tid]      = w[((op * 2 + 0) * 32 + ic) * 64 + tid];
        s_w2[64 + tid] = w[((op * 2 + 1) * 32 + ic) * 64 + tid];
        const float* hin = g_h1 + (n * 32 + ic) * 729;
#pragma unroll 1
        for (int zz = 0; zz < 11; zz++) {
            int iz = zz - 1;
            bool ok = (unsigned)iz < 9u;
            const float* src = hin + iz * 81;
            s_in[zz * 132 + tid]      = (ok && goff[0] >= 0) ? src[goff[0]] : 0.f;
            s_in[zz * 132 + 64 + tid] = (ok && goff[1] >= 0) ? src[goff[1]] : 0.f;
            if (tid < 4)
                s_in[zz * 132 + 128 + tid] = (ok && goff[2] >= 0) ? src[goff[2]] : 0.f;
        }
        __syncthreads();

#pragma unroll 1
        for (int kz = 0; kz < 4; kz++) {
#pragma unroll
            for (int ky = 0; ky < 4; ky++) {
                ull wp0[4], wp1[4];
#pragma unroll
                for (int kx = 0; kx < 4; kx++) {
                    float a0 = s_w2[(kz * 4 + ky) * 4 + kx];
                    float b0 = s_w2[64 + (kz * 4 + ky) * 4 + kx];
                    wp0[kx] = pack2(a0, a0);
                    wp1[kx] = pack2(b0, b0);
                }
#pragma unroll
                for (int dz = 0; dz < 2; dz++) {
#pragma unroll
                    for (int dy = 0; dy < 2; dy++) {
                        const float* row = s_in + (2 * pz + dz + kz) * 132
                                         + (2 * py + dy + ky) * 12 + 2 * px;
                        const ull* r2 = (const ull*)row;
                        ull e0 = r2[0], e1 = r2[1], e2 = r2[2];
                        float v0, v1, v2, v3, v4, v5;
                        unpack2(e0, v0, v1); unpack2(e1, v2, v3); unpack2(e2, v4, v5);
                        ull P[4];
                        P[0] = e0; P[2] = e1;
                        P[1] = pack2(v1, v2); P[3] = pack2(v3, v4);
                        const int dd = dz * 2 + dy;
#pragma unroll
                        for (int kx = 0; kx < 4; kx++) {
                            fma2(A[0][dd], P[kx], wp0[kx]);
                            fma2(A[1][dd], P[kx], wp1[kx]);
                        }
                    }
                }
            }
        }
    }

    const float a = alpha[0];
#pragma unroll
    for (int o = 0; o < 2; o++) {
        float bs = bias[op * 2 + o];
        float m = -CUDART_INF_F;
#pragma unroll
        for (int dd = 0; dd < 4; dd++) {
            float lo, hi;
            unpack2(A[o][dd], lo, hi);
            lo += bs; lo = lo >= 0.f ? lo : a * lo;
            hi += bs; hi = hi >= 0.f ? hi : a * hi;
            m = fmaxf(m, fmaxf(lo, hi));
        }
        g_h2[(n * 64 + op * 2 + o) * 64 + tid] = m;
    }
}

// ---------------------------------------------------------------------------
// Stage 3: conv(64->64,k3,p0) + prelu -> feat [80,512]
// grid (n=80, half=2), block 256 = 32 oc x 8 positions
// ---------------------------------------------------------------------------
__global__ __launch_bounds__(256) void conv3_kernel(
    const float* __restrict__ w, const float* __restrict__ bias,
    const float* __restrict__ alpha)
{
    __shared__ float s_in[4096];
    const int n = blockIdx.x;
    const int half = blockIdx.y;
    const int tid = threadIdx.x;

    for (int t = tid; t < 4096; t += 256) s_in[t] = g_h2[n * 4096 + t];
    __syncthreads();

    const int oc = half * 32 + (tid >> 3), pos = tid & 7;
    const int z = pos >> 2, y = (pos >> 1) & 1, x0 = pos & 1;

    float a0 = 0.f, a1 = 0.f, a2 = 0.f, a3 = 0.f;
    const float* wr = w + oc * (64 * 27);
#pragma unroll 1
    for (int ic = 0; ic < 64; ic += 4) {
#pragma unroll
        for (int u = 0; u < 4; u++) {
            const float* si = s_in + (ic + u) * 64;
            const float* wi = wr + (ic + u) * 27;
            float s = 0.f;
#pragma unroll
            for (int kz = 0; kz < 3; kz++)
#pragma unroll
                for (int ky = 0; ky < 3; ky++)
#pragma unroll
                    for (int kx = 0; kx < 3; kx++)
                        s += wi[(kz * 3 + ky) * 3 + kx]
                           * si[(z + kz) * 16 + (y + ky) * 4 + (x0 + kx)];
            if (u == 0) a0 += s; else if (u == 1) a1 += s;
            else if (u == 2) a2 += s; else a3 += s;
        }
    }
    float acc = bias[oc] + (a0 + a1) + (a2 + a3);
    const float a = alpha[0];
    acc = acc >= 0.f ? acc : a * acc;
    g_feat[n * 512 + oc * 8 + pos] = acc;
}

// ---------------------------------------------------------------------------
// Comm-FC layers
// ---------------------------------------------------------------------------
__device__ __forceinline__ void fc_body(
    const float* __restrict__ fin, const float* __restrict__ w,
    const float* __restrict__ bias, const float* __restrict__ alpha,
    float* __restrict__ fout, int D, int O)
{
    __shared__ float cat[1024];
    const int n = blockIdx.x;
    const int b = n / 5, a = n % 5;
    const int tid = threadIdx.x;

    for (int i = tid; i < D; i += 256) {
        cat[i] = fin[n * D + i];
        float s = 0.f;
#pragma unroll
        for (int a2 = 0; a2 < 5; a2++) s += fin[(b * 5 + a2) * D + i];
        cat[D + i] = s * 0.2f;
    }
    __syncthreads();

    if (tid < O) {
        float accv = bias[a * O + tid];
        const float4* w4 = (const float4*)(w + (size_t)(a * O + tid) * (2 * D));
        const float4* c4 = (const float4*)cat;
        float4 s4 = make_float4(0.f, 0.f, 0.f, 0.f);
        const int n4 = (2 * D) / 4;
        for (int i = 0; i < n4; i++) {
            float4 wv = w4[i];
            float4 cv = c4[i];
            s4.x += wv.x * cv.x; s4.y += wv.y * cv.y;
            s4.z += wv.z * cv.z; s4.w += wv.w * cv.w;
        }
        accv += (s4.x + s4.y) + (s4.z + s4.w);
        if (alpha) {
            float al = alpha[0];
            accv = accv >= 0.f ? accv : al * accv;
        }
        fout[n * O + tid] = accv;
    }
}

__global__ __launch_bounds__(256) void fc1_kernel(const float* __restrict__ w,
                                                  const float* __restrict__ b,
                                                  const float* __restrict__ al)
{ fc_body(g_feat, w, b, al, g_f1, 512, 256); }

__global__ __launch_bounds__(256) void fc2_kernel(const float* __restrict__ w,
                                                  const float* __restrict__ b,
                                                  const float* __restrict__ al)
{ fc_body(g_f1, w, b, al, g_f2, 256, 128); }

__global__ __launch_bounds__(256) void fc3_kernel(const float* __restrict__ w,
                                                  const float* __restrict__ b,
                                                  float* __restrict__ out)
{ fc_body(g_f2, w, b, nullptr, out, 128, 6); }

// ---------------------------------------------------------------------------
extern "C" void kernel_launch(void* const* d_in, const int* in_sizes, int n_in,
                              void* d_out, int out_size)
{
    const float* x   = (const float*)d_in[0];
    const float* w0  = (const float*)d_in[1];
    const float* b0  = (const float*)d_in[2];
    const float* a0  = (const float*)d_in[3];
    const float* w1  = (const float*)d_in[4];
    const float* b1  = (const float*)d_in[5];
    const float* a1  = (const float*)d_in[6];
    const float* w2  = (const float*)d_in[7];
    const float* b2  = (const float*)d_in[8];
    const float* a2  = (const float*)d_in[9];
    const float* w3  = (const float*)d_in[10];
    const float* b3  = (const float*)d_in[11];
    const float* a3  = (const float*)d_in[12];
    const float* fw1 = (const float*)d_in[13];
    const float* fb1 = (const float*)d_in[14];
    const float* a4  = (const float*)d_in[15];
    const float* fw2 = (const float*)d_in[16];
    const float* fb2 = (const float*)d_in[17];
    const float* a5  = (const float*)d_in[18];
    const float* fw3 = (const float*)d_in[19];
    const float* fb3 = (const float*)d_in[20];

    const int smem0 = (13248 + 1000) * sizeof(float);
    cudaFuncSetAttribute(conv0_kernel, cudaFuncAttributeMaxDynamicSharedMemorySize, smem0);

    conv0_kernel<<<dim3(21, 16, 80), 256, smem0>>>(x, w0, b0, a0);
    conv1_kernel<<<dim3(16, 80), 256>>>(w1, b1, a1);
    conv2_kernel<<<dim3(32, 80), 64>>>(w2, b2, a2);
    conv3_kernel<<<dim3(80, 2), 256>>>(w3, b3, a3);
    fc1_kernel<<<80, 256>>>(fw1, fb1, a4);
    fc2_kernel<<<80, 256>>>(fw2, fb2, a5);
    fc3_kernel<<<80, 256>>>(fw3, fb3, (float*)d_out);
}

// round 17
// speedup vs baseline: 1.5996x; 1.5902x over previous
#include <cuda_runtime.h>
#include <cuda_bf16.h>
#include <math_constants.h>

// CommNet forward. conv0/conv2/conv3/fc: scalar fp32 (at datapath roof).
// conv1 (32->32, k5, p1, 60% of MACs): tensor-core mma.sync m16n8k16
// split-bf16 implicit GEMM:
//   GEMM: D[oc=32, pos] = sum_{k=4000} W[oc,k] X[k,pos], k = (tap,ic)
//   3-pass split: W~Wh+Wl, X~Xh+Xl, D = WhXh + WhXl + WlXh  (err ~1.5e-5)
// Pipeline: w1_prepack (weights -> fragment-ordered bf16 hi/lo)
//           c1_convert (g_h0 fp32 -> padded channel-last bf16 hi/lo)
//           conv1_mma  (pure MMA+LDG, no smem/barriers) -> fp32 scratch
//           pool1      (bias + prelu + maxpool2 -> g_h1)
// conv1_mma is app launch idx 3 = the ncu capture slot (per R1/R6).

typedef unsigned long long ull;
typedef unsigned int uint;

__device__ __forceinline__ ull pack2(float lo, float hi) {
    ull d; asm("mov.b64 %0, {%1, %2};" : "=l"(d) : "f"(lo), "f"(hi)); return d;
}
__device__ __forceinline__ void unpack2(ull v, float& lo, float& hi) {
    asm("mov.b64 {%0, %1}, %2;" : "=f"(lo), "=f"(hi) : "l"(v));
}
__device__ __forceinline__ void fma2(ull& d, ull a, ull b) {
    asm("fma.rn.f32x2 %0, %1, %2, %0;" : "+l"(d) : "l"(a), "l"(b));
}

// ---- buffers ----
__device__ float g_h0[80 * 32 * 21 * 21 * 21];     // conv0 out, 94.8 MB
__device__ float g_h1[80 * 32 * 9 * 9 * 9];
__device__ float g_h2[80 * 64 * 64];
__device__ float g_feat[80 * 512];
__device__ float g_f1[80 * 256];
__device__ float g_f2[80 * 128];

// conv1 tensor-path buffers
// input, padded channel-last: [n][z22][y22][x28][icp16] x {hi,lo} words
#define C1_PX 16            // uint2-pairs per x step (16 icp)
#define C1_PY 448           // 28 * 16
#define C1_PZ 9856          // 22 * 448
#define C1_PN 216832        // 22 * 9856
__device__ uint2 g_c1in[80 * 216832];               // 138.8 MB
__device__ uint4 g_w1h[16000];                      // 250 ksteps x 2 mtiles x 32 lanes
__device__ uint4 g_w1l[16000];
// conv1 raw output: [n][oc32][z18][y18][x24] fp32 (x>=18 garbage, unread)
#define C1O_N 248832        // 32 * 7776
__device__ float g_c1out[80 * 248832];              // 79.6 MB

// split float -> (bf16 hi, bf16 lo) packed pairs (element0 in low half)
__device__ __forceinline__ void split_pack(float v0, float v1, uint& hi, uint& lo)
{
    __nv_bfloat16 h0 = __float2bfloat16(v0);
    __nv_bfloat16 h1 = __float2bfloat16(v1);
    float r0 = v0 - __bfloat162float(h0);
    float r1 = v1 - __bfloat162float(h1);
    __nv_bfloat16 l0 = __float2bfloat16(r0);
    __nv_bfloat16 l1 = __float2bfloat16(r1);
    hi = ((uint)__bfloat16_as_ushort(h1) << 16) | (uint)__bfloat16_as_ushort(h0);
    lo = ((uint)__bfloat16_as_ushort(l1) << 16) | (uint)__bfloat16_as_ushort(l0);
}

__device__ __forceinline__ void mma16816(float d[4], uint4 a, uint b0, uint b1)
{
    asm("mma.sync.aligned.m16n8k16.row.col.f32.bf16.bf16.f32 "
        "{%0,%1,%2,%3}, {%4,%5,%6,%7}, {%8,%9}, {%0,%1,%2,%3};"
        : "+f"(d[0]), "+f"(d[1]), "+f"(d[2]), "+f"(d[3])
        : "r"(a.x), "r"(a.y), "r"(a.z), "r"(a.w), "r"(b0), "r"(b1));
}

// ---------------------------------------------------------------------------
// Stage 0: conv(4->32,k5,p1) + prelu + maxpool2, fused, f32x2 (unchanged).
// ---------------------------------------------------------------------------
#define C0_PLANE 2208   // 46*48

__global__ __launch_bounds__(256) void conv0_kernel(
    const float* __restrict__ x, const float* __restrict__ w,
    const float* __restrict__ bias, const float* __restrict__ alpha)
{
    extern __shared__ float sm[];
    float* s_in = sm;                 // 6*2208 = 13248
    float* s_w  = sm + 13248;         // 1000

    const int pz = blockIdx.x;
    const int op = blockIdx.y;
    const int n  = blockIdx.z;
    const int tid = threadIdx.x;

    for (int t = tid; t < 1000; t += 256) {
        int o = t / 500, r = t % 500;
        s_w[t] = w[(op * 2 + o) * 500 + r];
    }

    int goff[9];
#pragma unroll
    for (int j = 0; j < 9; j++) {
        int idx = tid + j * 256;
        int yy = idx / 48, xx = idx % 48;
        bool v = (idx < 2208) && (xx >= 1 && xx <= 45) && (yy >= 1 && yy <= 45);
        goff[j] = v ? ((yy - 1) * 45 + (xx - 1)) : -1;
    }

    const int py = tid / 11, pxq = tid % 11;
    const bool active = tid < 231;

    ull A[2][2][4];
#pragma unroll
    for (int o = 0; o < 2; o++)
#pragma unroll
        for (int X = 0; X < 2; X++)
#pragma unroll
            for (int d = 0; d < 4; d++) A[o][X][d] = 0ull;

    for (int ic = 0; ic < 4; ic++) {
        __syncthreads();
        const float* xin = x + (n * 4 + ic) * 91125;
#pragma unroll
        for (int zz = 0; zz < 6; zz++) {
            int iz = 2 * pz - 1 + zz;
            bool izok = (unsigned)iz < 45u;
            const float* src = xin + iz * 2025;
#pragma unroll
            for (int j = 0; j < 8; j++) {
                float v = (izok && goff[j] >= 0) ? src[goff[j]] * (1.0f / 255.0f) : 0.f;
                s_in[zz * C0_PLANE + tid + j * 256] = v;
            }
            if (tid < 160) {
                float v = (izok && goff[8] >= 0) ? src[goff[8]] * (1.0f / 255.0f) : 0.f;
                s_in[zz * C0_PLANE + tid + 2048] = v;
            }
        }
        __syncthreads();
        if (!active) continue;

        const float* wb0 = s_w + ic * 125;
        const float* wb1 = s_w + 500 + ic * 125;
#pragma unroll 1
        for (int kz = 0; kz < 5; kz++) {
#pragma unroll 1
            for (int ky = 0; ky < 5; ky++) {
                ull wp0[5], wp1[5];
#pragma unroll
                for (int kx = 0; kx < 5; kx++) {
                    float a0 = wb0[(kz * 5 + ky) * 5 + kx];
                    float b0 = wb1[(kz * 5 + ky) * 5 + kx];
                    wp0[kx] = pack2(a0, a0);
                    wp1[kx] = pack2(b0, b0);
                }
#pragma unroll
                for (int dz = 0; dz < 2; dz++) {
#pragma unroll
                    for (int dy = 0; dy < 2; dy++) {
                        const float* row = s_in + (kz + dz) * C0_PLANE
                                         + (2 * py + dy + ky) * 48 + 4 * pxq;
                        const ull* r2 = (const ull*)row;
                        ull e0 = r2[0], e1 = r2[1], e2 = r2[2], e3 = r2[3];
                        float v0, v1, v2, v3, v4, v5, v6, v7;
                        unpack2(e0, v0, v1); unpack2(e1, v2, v3);
                        unpack2(e2, v4, v5); unpack2(e3, v6, v7);
                        ull P[7];
                        P[0] = e0; P[2] = e1; P[4] = e2; P[6] = e3;
                        P[1] = pack2(v1, v2); P[3] = pack2(v3, v4); P[5] = pack2(v5, v6);
                        const int dd = dz * 2 + dy;
#pragma unroll
                        for (int kx = 0; kx < 5; kx++) {
                            fma2(A[0][0][dd], P[kx],     wp0[kx]);
                            fma2(A[1][0][dd], P[kx],     wp1[kx]);
                            fma2(A[0][1][dd], P[kx + 2], wp0[kx]);
                            fma2(A[1][1][dd], P[kx + 2], wp1[kx]);
                        }
                    }
                }
            }
        }
    }

    if (active) {
        const float a = alpha[0];
#pragma unroll
        for (int o = 0; o < 2; o++) {
            float bs = bias[op * 2 + o];
#pragma unroll
            for (int X = 0; X < 2; X++) {
                int pxx = 2 * pxq + X;
                if (pxx < 21) {
                    float m = -CUDART_INF_F;
#pragma unroll
                    for (int dd = 0; dd < 4; dd++) {
                        float lo, hi;
                        unpack2(A[o][X][dd], lo, hi);
                        lo += bs; lo = lo >= 0.f ? lo : a * lo;
                        hi += bs; hi = hi >= 0.f ? hi : a * hi;
                        m = fmaxf(m, fmaxf(lo, hi));
                    }
                    g_h0[((n * 32 + op * 2 + o) * 21 + pz) * 441 + py * 21 + pxx] = m;
                }
            }
        }
    }
}

// ---------------------------------------------------------------------------
// conv1 tensor path, kernel 1: weight prepack into fragment order.
// i indexes (kstep s, mtile m, lane): uint4 = regs a0..a3.
// A fragment (m16n8k16 row-major): a0=(g, 2t..+1) a1=(g+8, 2t..+1)
//                                  a2=(g, 2t+8..+9) a3=(g+8, 2t+8..+9)
// k order: s -> tap = s>>1, ichalf = s&1; k_local -> ic = ichalf*16 + k_local
// ---------------------------------------------------------------------------
__global__ void w1_prepack_kernel(const float* __restrict__ w1)
{
    int i = blockIdx.x * 256 + threadIdx.x;
    if (i >= 16000) return;
    int lane = i & 31, mrem = i >> 5;
    int m = mrem & 1, s = mrem >> 1;
    int gg = lane >> 2, tq = lane & 3;
    int tap = s >> 1, ichalf = s & 1;
    uint hw[4], lw[4];
#pragma unroll
    for (int r = 0; r < 4; r++) {
        int oc = m * 16 + gg + ((r & 1) << 3);
        int ic = ichalf * 16 + tq * 2 + ((r >> 1) << 3);
        float v0 = w1[(oc * 32 + ic) * 125 + tap];
        float v1 = w1[(oc * 32 + ic + 1) * 125 + tap];
        split_pack(v0, v1, hw[r], lw[r]);
    }
    g_w1h[i] = make_uint4(hw[0], hw[1], hw[2], hw[3]);
    g_w1l[i] = make_uint4(lw[0], lw[1], lw[2], lw[3]);
}

// ---------------------------------------------------------------------------
// conv1 tensor path, kernel 2: convert g_h0 -> padded channel-last bf16 hi/lo.
// storage idx = input coord + 1 (pad); OOB -> 0. grid (484=z22*y22, n80), blk 448.
// ---------------------------------------------------------------------------
__global__ __launch_bounds__(448) void c1_convert_kernel()
{
    const int n = blockIdx.y;
    const int zy = blockIdx.x;            // z*22 + y
    const int tid = threadIdx.x;          // x*16 + icp
    const int x = tid >> 4, icp = tid & 15;
    const int z = zy / 22, y = zy % 22;
    const int iz = z - 1, iy = y - 1, ix = x - 1;
    float v0 = 0.f, v1 = 0.f;
    if ((unsigned)iz < 21u && (unsigned)iy < 21u && (unsigned)ix < 21u) {
        const float* src = g_h0 + (n * 32 + icp * 2) * 9261 + iz * 441 + iy * 21 + ix;
        v0 = src[0];
        v1 = src[9261];
    }
    uint hi, lo;
    split_pack(v0, v1, hi, lo);
    g_c1in[n * C1_PN + zy * C1_PY + x * C1_PX + icp] = make_uint2(hi, lo);
}

// ---------------------------------------------------------------------------
// conv1 tensor path, kernel 3: the MMA mainloop.
// Warp W handles 6 n-tiles (48 positions); 162 warps/sample; grid (21, 80).
// Per k-step: 4x LDG.128 A-fragments, 12x LDG.64 B (hi+lo in one uint2),
// 36 MMAs (6 tiles x 2 mtiles x 3 passes), dependency distance 6.
// B fragment (col): b0 = k rows 2t,2t+1 @ col g; b1 = +8.
// D: c0=(g,2t) c1=(g,2t+1) c2=(g+8,2t) c3=(g+8,2t+1).
// ---------------------------------------------------------------------------
__global__ __launch_bounds__(256) void conv1_mma_kernel()
{
    const int n = blockIdx.y;
    const int tid = threadIdx.x;
    const int W = blockIdx.x * 8 + (tid >> 5);
    if (W >= 162) return;
    const int lane = tid & 31;
    const int g = lane >> 2, tq = lane & 3;

    // tile t -> xt = t%3 (x base = xt*8), y = (t/3)%18, z = t/54
    int pb[6];
#pragma unroll
    for (int j = 0; j < 6; j++) {
        int t = W * 6 + j;
        int xt = t % 3, y = (t / 3) % 18, z = t / 54;
        pb[j] = z * C1_PZ + y * C1_PY + (xt * 8 + g) * C1_PX + tq;
    }

    float D[6][2][4];
#pragma unroll
    for (int j = 0; j < 6; j++)
#pragma unroll
        for (int m = 0; m < 2; m++)
#pragma unroll
            for (int r = 0; r < 4; r++) D[j][m][r] = 0.f;

    const uint2* __restrict__ in2 = g_c1in + n * C1_PN;

#pragma unroll 1
    for (int s = 0; s < 250; s++) {
        const int tap = s >> 1, ichalf = s & 1;
        const int kz = tap / 25, rr = tap % 25;
        const int ky = rr / 5, kx = rr % 5;
        const int off = kz * C1_PZ + ky * C1_PY + kx * C1_PX + ichalf * 8;

        const uint4 Ah0 = g_w1h[s * 64 + lane];
        const uint4 Ah1 = g_w1h[s * 64 + 32 + lane];
        const uint4 Al0 = g_w1l[s * 64 + lane];
        const uint4 Al1 = g_w1l[s * 64 + 32 + lane];

        uint Bh[6][2], Bl[6][2];
#pragma unroll
        for (int j = 0; j < 6; j++) {
            uint2 u0 = in2[pb[j] + off];
            uint2 u1 = in2[pb[j] + off + 4];
            Bh[j][0] = u0.x; Bl[j][0] = u0.y;
            Bh[j][1] = u1.x; Bl[j][1] = u1.y;
        }
        // pass Wh*Xh
#pragma unroll
        for (int j = 0; j < 6; j++) mma16816(D[j][0], Ah0, Bh[j][0], Bh[j][1]);
#pragma unroll
        for (int j = 0; j < 6; j++) mma16816(D[j][1], Ah1, Bh[j][0], Bh[j][1]);
        // pass Wh*Xl
#pragma unroll
        for (int j = 0; j < 6; j++) mma16816(D[j][0], Ah0, Bl[j][0], Bl[j][1]);
#pragma unroll
        for (int j = 0; j < 6; j++) mma16816(D[j][1], Ah1, Bl[j][0], Bl[j][1]);
        // pass Wl*Xh
#pragma unroll
        for (int j = 0; j < 6; j++) mma16816(D[j][0], Al0, Bh[j][0], Bh[j][1]);
#pragma unroll
        for (int j = 0; j < 6; j++) mma16816(D[j][1], Al1, Bh[j][0], Bh[j][1]);
    }

    float* outb = g_c1out + n * C1O_N;
#pragma unroll
    for (int j = 0; j < 6; j++) {
        int t = W * 6 + j;
        int xt = t % 3, y = (t / 3) % 18, z = t / 54;
        int base = z * 432 + y * 24 + xt * 8 + tq * 2;
#pragma unroll
        for (int m = 0; m < 2; m++) {
            int oc = m * 16 + g;
            *(float2*)(outb + oc * 7776 + base)       = make_float2(D[j][m][0], D[j][m][1]);
            *(float2*)(outb + (oc + 8) * 7776 + base) = make_float2(D[j][m][2], D[j][m][3]);
        }
    }
}

// ---------------------------------------------------------------------------
// conv1 tensor path, kernel 4: bias + prelu + maxpool2 -> g_h1.
// ---------------------------------------------------------------------------
__global__ __launch_bounds__(256) void pool1_kernel(
    const float* __restrict__ bias, const float* __restrict__ alpha)
{
    const int oc = blockIdx.x, n = blockIdx.y;
    const float b = bias[oc], al = alpha[0];
    const float* src = g_c1out + n * C1O_N + oc * 7776;
    float* dst = g_h1 + (n * 32 + oc) * 729;
    for (int t = threadIdx.x; t < 729; t += 256) {
        int pz = t / 81, r = t % 81, py = r / 9, px = r % 9;
        const float* s0 = src + 2 * pz * 432 + 2 * py * 24 + 2 * px;
        float m = -CUDART_INF_F;
#pragma unroll
        for (int dz = 0; dz < 2; dz++)
#pragma unroll
            for (int dy = 0; dy < 2; dy++)
#pragma unroll
                for (int dx = 0; dx < 2; dx++) {
                    float v = s0[dz * 432 + dy * 24 + dx] + b;
                    v = v >= 0.f ? v : al * v;
                    m = fmaxf(m, v);
                }
        dst[t] = m;
    }
}

// ---------------------------------------------------------------------------
// Stage 2: conv(32->64,k4,p1) + prelu + maxpool2, fused, f32x2 (unchanged).
// ---------------------------------------------------------------------------
__global__ __launch_bounds__(64) void conv2_kernel(
    const float* __restrict__ w, const float* __restrict__ bias,
    const float* __restrict__ alpha)
{
    __shared__ float s_in[11 * 132];
    __shared__ float s_w2[128];

    const int op = blockIdx.x;
    const int n  = blockIdx.y;
    const int tid = threadIdx.x;
    const int pz = tid >> 4, py = (tid >> 2) & 3, px = tid & 3;

    int goff[3];
#pragma unroll
    for (int j = 0; j < 3; j++) {
        int idx = tid + j * 64;
        int yy = idx / 12, xx = idx % 12;
        bool v = (idx < 132) && (xx >= 1 && xx <= 9) && (yy >= 1 && yy <= 9);
        goff[j] = v ? ((yy - 1) * 9 + (xx - 1)) : -1;
    }

    ull A[2][4];
#pragma unroll
    for (int o = 0; o < 2; o++)
#pragma unroll
        for (int d = 0; d < 4; d++) A[o][d] = 0ull;

    for (int ic = 0; ic < 32; ic++) {
        __syncthreads();
        s_w2[tid]      = w[((op * 2 + 0) * 32 + ic) * 64 + tid];
        s_w2[64 + tid] = w[((op * 2 + 1) * 32 + ic) * 64 + tid];
        const float* hin = g_h1 + (n * 32 + ic) * 729;
#pragma unroll 1
        for (int zz = 0; zz < 11; zz++) {
            int iz = zz - 1;
            bool ok = (unsigned)iz < 9u;
            const float* src = hin + iz * 81;
            s_in[zz * 132 + tid]      = (ok && goff[0] >= 0) ? src[goff[0]] : 0.f;
            s_in[zz * 132 + 64 + tid] = (ok && goff[1] >= 0) ? src[goff[1]] : 0.f;
            if (tid < 4)
                s_in[zz * 132 + 128 + tid] = (ok && goff[2] >= 0) ? src[goff[2]] : 0.f;
        }
        __syncthreads();

#pragma unroll 1
        for (int kz = 0; kz < 4; kz++) {
#pragma unroll
            for (int ky = 0; ky < 4; ky++) {
                ull wp0[4], wp1[4];
#pragma unroll
                for (int kx = 0; kx < 4; kx++) {
                    float a0 = s_w2[(kz * 4 + ky) * 4 + kx];
                    float b0 = s_w2[64 + (kz * 4 + ky) * 4 + kx];
                    wp0[kx] = pack2(a0, a0);
                    wp1[kx] = pack2(b0, b0);
                }
#pragma unroll
                for (int dz = 0; dz < 2; dz++) {
#pragma unroll
                    for (int dy = 0; dy < 2; dy++) {
                        const float* row = s_in + (2 * pz + dz + kz) * 132
                                         + (2 * py + dy + ky) * 12 + 2 * px;
                        const ull* r2 = (const ull*)row;
                        ull e0 = r2[0], e1 = r2[1], e2 = r2[2];
                        float v0, v1, v2, v3, v4, v5;
                        unpack2(e0, v0, v1); unpack2(e1, v2, v3); unpack2(e2, v4, v5);
                        ull P[4];
                        P[0] = e0; P[2] = e1;
                        P[1] = pack2(v1, v2); P[3] = pack2(v3, v4);
                        const int dd = dz * 2 + dy;
#pragma unroll
                        for (int kx = 0; kx < 4; kx++) {
                            fma2(A[0][dd], P[kx], wp0[kx]);
                            fma2(A[1][dd], P[kx], wp1[kx]);
                        }
                    }
                }
            }
        }
    }

    const float a = alpha[0];
#pragma unroll
    for (int o = 0; o < 2; o++) {
        float bs = bias[op * 2 + o];
        float m = -CUDART_INF_F;
#pragma unroll
        for (int dd = 0; dd < 4; dd++) {
            float lo, hi;
            unpack2(A[o][dd], lo, hi);
            lo += bs; lo = lo >= 0.f ? lo : a * lo;
            hi += bs; hi = hi >= 0.f ? hi : a * hi;
            m = fmaxf(m, fmaxf(lo, hi));
        }
        g_h2[(n * 64 + op * 2 + o) * 64 + tid] = m;
    }
}

// ---------------------------------------------------------------------------
// Stage 3: conv(64->64,k3,p0) + prelu -> feat [80,512] (unchanged).
// ---------------------------------------------------------------------------
__global__ __launch_bounds__(256) void conv3_kernel(
    const float* __restrict__ w, const float* __restrict__ bias,
    const float* __restrict__ alpha)
{
    __shared__ float s_in[4096];
    const int n = blockIdx.x;
    const int half = blockIdx.y;
    const int tid = threadIdx.x;

    for (int t = tid; t < 4096; t += 256) s_in[t] = g_h2[n * 4096 + t];
    __syncthreads();

    const int oc = half * 32 + (tid >> 3), pos = tid & 7;
    const int z = pos >> 2, y = (pos >> 1) & 1, x0 = pos & 1;

    float a0 = 0.f, a1 = 0.f, a2 = 0.f, a3 = 0.f;
    const float* wr = w + oc * (64 * 27);
#pragma unroll 1
    for (int ic = 0; ic < 64; ic += 4) {
#pragma unroll
        for (int u = 0; u < 4; u++) {
            const float* si = s_in + (ic + u) * 64;
            const float* wi = wr + (ic + u) * 27;
            float s = 0.f;
#pragma unroll
            for (int kz = 0; kz < 3; kz++)
#pragma unroll
                for (int ky = 0; ky < 3; ky++)
#pragma unroll
                    for (int kx = 0; kx < 3; kx++)
                        s += wi[(kz * 3 + ky) * 3 + kx]
                           * si[(z + kz) * 16 + (y + ky) * 4 + (x0 + kx)];
            if (u == 0) a0 += s; else if (u == 1) a1 += s;
            else if (u == 2) a2 += s; else a3 += s;
        }
    }
    float acc = bias[oc] + (a0 + a1) + (a2 + a3);
    const float a = alpha[0];
    acc = acc >= 0.f ? acc : a * acc;
    g_feat[n * 512 + oc * 8 + pos] = acc;
}

// ---------------------------------------------------------------------------
// Comm-FC layers (unchanged)
// ---------------------------------------------------------------------------
__device__ __forceinline__ void fc_body(
    const float* __restrict__ fin, const float* __restrict__ w,
    const float* __restrict__ bias, const float* __restrict__ alpha,
    float* __restrict__ fout, int D, int O)
{
    __shared__ float cat[1024];
    const int n = blockIdx.x;
    const int b = n / 5, a = n % 5;
    const int tid = threadIdx.x;

    for (int i = tid; i < D; i += 256) {
        cat[i] = fin[n * D + i];
        float s = 0.f;
#pragma unroll
        for (int a2 = 0; a2 < 5; a2++) s += fin[(b * 5 + a2) * D + i];
        cat[D + i] = s * 0.2f;
    }
    __syncthreads();

    if (tid < O) {
        float accv = bias[a * O + tid];
        const float4* w4 = (const float4*)(w + (size_t)(a * O + tid) * (2 * D));
        const float4* c4 = (const float4*)cat;
        float4 s4 = make_float4(0.f, 0.f, 0.f, 0.f);
        const int n4 = (2 * D) / 4;
        for (int i = 0; i < n4; i++) {
            float4 wv = w4[i];
            float4 cv = c4[i];
            s4.x += wv.x * cv.x; s4.y += wv.y * cv.y;
            s4.z += wv.z * cv.z; s4.w += wv.w * cv.w;
        }
        accv += (s4.x + s4.y) + (s4.z + s4.w);
        if (alpha) {
            float al = alpha[0];
            accv = accv >= 0.f ? accv : al * accv;
        }
        fout[n * O + tid] = accv;
    }
}

__global__ __launch_bounds__(256) void fc1_kernel(const float* __restrict__ w,
                                                  const float* __restrict__ b,
                                                  const float* __restrict__ al)
{ fc_body(g_feat, w, b, al, g_f1, 512, 256); }

__global__ __launch_bounds__(256) void fc2_kernel(const float* __restrict__ w,
                                                  const float* __restrict__ b,
                                                  const float* __restrict__ al)
{ fc_body(g_f1, w, b, al, g_f2, 256, 128); }

__global__ __launch_bounds__(256) void fc3_kernel(const float* __restrict__ w,
                                                  const float* __restrict__ b,
                                                  float* __restrict__ out)
{ fc_body(g_f2, w, b, nullptr, out, 128, 6); }

// ---------------------------------------------------------------------------
extern "C" void kernel_launch(void* const* d_in, const int* in_sizes, int n_in,
                              void* d_out, int out_size)
{
    const float* x   = (const float*)d_in[0];
    const float* w0  = (const float*)d_in[1];
    const float* b0  = (const float*)d_in[2];
    const float* a0  = (const float*)d_in[3];
    const float* w1  = (const float*)d_in[4];
    const float* b1  = (const float*)d_in[5];
    const float* a1  = (const float*)d_in[6];
    const float* w2  = (const float*)d_in[7];
    const float* b2  = (const float*)d_in[8];
    const float* a2  = (const float*)d_in[9];
    const float* w3  = (const float*)d_in[10];
    const float* b3  = (const float*)d_in[11];
    const float* a3  = (const float*)d_in[12];
    const float* fw1 = (const float*)d_in[13];
    const float* fb1 = (const float*)d_in[14];
    const float* a4  = (const float*)d_in[15];
    const float* fw2 = (const float*)d_in[16];
    const float* fb2 = (const float*)d_in[17];
    const float* a5  = (const float*)d_in[18];
    const float* fw3 = (const float*)d_in[19];
    const float* fb3 = (const float*)d_in[20];

    const int smem0 = (13248 + 1000) * sizeof(float);
    cudaFuncSetAttribute(conv0_kernel, cudaFuncAttributeMaxDynamicSharedMemorySize, smem0);

    // idx 0..3; conv1_mma at idx 3 = ncu capture slot
    conv0_kernel<<<dim3(21, 16, 80), 256, smem0>>>(x, w0, b0, a0);
    w1_prepack_kernel<<<63, 256>>>(w1);
    c1_convert_kernel<<<dim3(484, 80), 448>>>();
    conv1_mma_kernel<<<dim3(21, 80), 256>>>();
    pool1_kernel<<<dim3(32, 80), 256>>>(b1, a1);
    conv2_kernel<<<dim3(32, 80), 64>>>(w2, b2, a2);
    conv3_kernel<<<dim3(80, 2), 256>>>(w3, b3, a3);
    fc1_kernel<<<80, 256>>>(fw1, fb1, a4);
    fc2_kernel<<<80, 256>>>(fw2, fb2, a5);
    fc3_kernel<<<80, 256>>>(fw3, fb3, (float*)d_out);
}